// round 17
// baseline (speedup 1.0000x reference)
#include <cuda_runtime.h>
#include <cuda_fp16.h>
#include <cstdint>

#define K_DIM 1024
#define M_DIM 2048
#define N_DIM 1024
#define NCHUNK 64
#define MT 1536            // tensor rows [0,1536), fp32 rows [1536,2048)

// Tensor fragments (m16n8k16 order), A only for m < MT (96 mfrags)
__device__ uint4 g_Ahi[(size_t)NCHUNK * 96 * 32];
__device__ uint4 g_Alo[(size_t)NCHUNK * 96 * 32];
__device__ uint4 g_Bfr[(size_t)NCHUNK * 128 * 32];
// fp32 operands: XC = (x_c)/16 transposed [k][m'] (512 rows), WC = w_c [k][n]
__device__ float g_XC[(size_t)K_DIM * 512];
__device__ float g_WC[(size_t)K_DIM * N_DIM];

// ---------------------------------------------------------------------------
// Prep: blocks [0,384) X-fragments (m<1536), [384,512) X-fp32 transpose,
// [512,768) W (fragments + WC). LUT in smem. Output zeroing folded in.
// ---------------------------------------------------------------------------
__global__ void prep_kernel(const float* __restrict__ X,
                            const float* __restrict__ W,
                            const float* __restrict__ vmap,
                            const float* __restrict__ wmap,
                            float4* __restrict__ outz) {
    __shared__ float s_lut[256];
    __shared__ unsigned sHi[256][9];
    __shared__ unsigned sLo[256][9];

    const int tid = threadIdx.x;
    const int gid = blockIdx.x * 256 + tid;
    const float4 z = make_float4(0.f, 0.f, 0.f, 0.f);
    outz[gid] = z;
    outz[gid + 196608] = z;
    if (gid + 393216 < 524288) outz[gid + 393216] = z;

    const bool isW = blockIdx.x >= 512;
    s_lut[tid] = isW ? wmap[tid] : vmap[tid];
    __syncthreads();

    if (blockIdx.x < 384) {
        // ---- X fragments for tensor region (rows < 1536)
        const int b = blockIdx.x;
        const int r = b / 6, m0b = (b % 6) * 256;
        const int m = m0b + tid;
        const float* src = X + (size_t)m * K_DIM + r * 16;
        float xs[16];
        ((float4*)xs)[0] = ((const float4*)src)[0];
        ((float4*)xs)[1] = ((const float4*)src)[1];
        ((float4*)xs)[2] = ((const float4*)src)[2];
        ((float4*)xs)[3] = ((const float4*)src)[3];
        unsigned hi[8], lo[8];
#pragma unroll
        for (int jj = 0; jj < 8; jj++) {
            unsigned short h[2], l[2];
#pragma unroll
            for (int e = 0; e < 2; e++) {
                int j = 2 * jj + e;
                float xv = xs[j];
                int idx = (int)(xv + 8.0f);
                idx = idx < 0 ? 0 : (idx > 15 ? 15 : idx);
                float xc = (xv + s_lut[j * 16 + idx]) * 0.0625f;
                __half hh = __float2half_rn(xc);
                __half ll = __float2half_rn(xc - __half2float(hh));
                h[e] = __half_as_ushort(hh);
                l[e] = __half_as_ushort(ll);
            }
            hi[jj] = h[0] | ((unsigned)h[1] << 16);
            lo[jj] = l[0] | ((unsigned)l[1] << 16);
        }
#pragma unroll
        for (int jj = 0; jj < 8; jj++) { sHi[tid][jj] = hi[jj]; sLo[tid][jj] = lo[jj]; }
        __syncthreads();
#pragma unroll
        for (int ss = 0; ss < 2; ss++) {
            int s = tid + 256 * ss;
            int f = s >> 5, l = s & 31, g = l >> 2, tq = l & 3;
            int r0 = f * 16 + g, r1 = r0 + 8;
            uint4 H = make_uint4(sHi[r0][tq], sHi[r1][tq], sHi[r0][tq + 4], sHi[r1][tq + 4]);
            uint4 L = make_uint4(sLo[r0][tq], sLo[r1][tq], sLo[r0][tq + 4], sLo[r1][tq + 4]);
            size_t gi = ((size_t)r * 96 + (m0b >> 4) + f) * 32 + l;
            g_Ahi[gi] = H;
            g_Alo[gi] = L;
        }
    } else if (blockIdx.x < 512) {
        // ---- X fp32 transpose for rows [1536,2048): XC[k][m'] = x_c/16
        int idx = (blockIdx.x - 384) * 256 + tid;   // 0..32767
        int r = idx >> 9, mp = idx & 511;
        const float* src = X + (size_t)(MT + mp) * K_DIM + r * 16;
        float xs[16];
        ((float4*)xs)[0] = ((const float4*)src)[0];
        ((float4*)xs)[1] = ((const float4*)src)[1];
        ((float4*)xs)[2] = ((const float4*)src)[2];
        ((float4*)xs)[3] = ((const float4*)src)[3];
#pragma unroll
        for (int e = 0; e < 16; e++) {
            float xv = xs[e];
            int ix = (int)(xv + 8.0f);
            ix = ix < 0 ? 0 : (ix > 15 ? 15 : ix);
            g_XC[(size_t)(r * 16 + e) * 512 + mp] = (xv + s_lut[e * 16 + ix]) * 0.0625f;
        }
    } else {
        // ---- W: fragments (full N) + WC fp32
        const int b = blockIdx.x - 512;
        const int r = b >> 2, n0b = (b & 3) * 256;
        const int n = n0b + tid;
        unsigned hi[8], lo[8];
#pragma unroll
        for (int jj = 0; jj < 8; jj++) {
            unsigned short h[2], l[2];
#pragma unroll
            for (int e = 0; e < 2; e++) {
                int j = 2 * jj + e;
                float w = W[(size_t)(16 * r + j) * N_DIM + n];
                int idx = (int)(w + 8.0f);
                idx = idx < 0 ? 0 : (idx > 15 ? 15 : idx);
                float wc = w + s_lut[j * 16 + idx];
                g_WC[(size_t)(16 * r + j) * N_DIM + n] = wc;
                __half hh = __float2half_rn(wc);
                __half ll = __float2half_rn(wc - __half2float(hh));
                h[e] = __half_as_ushort(hh);
                l[e] = __half_as_ushort(ll);
            }
            hi[jj] = h[0] | ((unsigned)h[1] << 16);
            lo[jj] = l[0] | ((unsigned)l[1] << 16);
        }
#pragma unroll
        for (int jj = 0; jj < 8; jj++) { sHi[tid][jj] = hi[jj]; sLo[tid][jj] = lo[jj]; }
        __syncthreads();
#pragma unroll
        for (int ss = 0; ss < 4; ss++) {
            int s = tid + 256 * ss;
            int f = s >> 5, l = s & 31, g = l >> 2, tq = l & 3;
            int nl = f * 8 + g;
            uint4 V = make_uint4(sHi[nl][tq], sHi[nl][tq + 4], sLo[nl][tq], sLo[nl][tq + 4]);
            g_Bfr[((size_t)r * 128 + (n0b >> 3) + f) * 32 + l] = V;
        }
    }
}

// ---------------------------------------------------------------------------
#define MMA_I(C, A, B0, B1)                                                    \
    asm("mma.sync.aligned.m16n8k16.row.col.f32.f16.f16.f32 "                   \
        "{%0,%1,%2,%3}, {%4,%5,%6,%7}, {%8,%9}, {%10,%10,%10,%10};"            \
        : "=f"((C)[0]), "=f"((C)[1]), "=f"((C)[2]), "=f"((C)[3])               \
        : "r"((A).x), "r"((A).y), "r"((A).z), "r"((A).w), "r"(B0), "r"(B1),    \
          "f"(0.0f))

#define MMA_A(C, A, B0, B1)                                                    \
    asm("mma.sync.aligned.m16n8k16.row.col.f32.f16.f16.f32 "                   \
        "{%0,%1,%2,%3}, {%4,%5,%6,%7}, {%8,%9}, {%0,%1,%2,%3};"                \
        : "+f"((C)[0]), "+f"((C)[1]), "+f"((C)[2]), "+f"((C)[3])               \
        : "r"((A).x), "r"((A).y), "r"((A).z), "r"((A).w), "r"(B0), "r"(B1))

#define FFMA2(ACC, A, B)                                                       \
    asm("fma.rn.f32x2 %0, %1, %2, %0;" : "+l"(ACC) : "l"(A), "l"(B))

// ---------------------------------------------------------------------------
// Main: heterogeneous. bid<148: TENSOR flavor (rows 0..1535, register-direct
// fragments, 8-chunk jobs). bid>=148: FP32 flavor (rows 1536..2047, R2 FFMA2
// engine, smem-staged, 8-chunk jobs). Flushes: atomicAdd of exact integers.
// ---------------------------------------------------------------------------
__global__ void __launch_bounds__(256, 2)
opu_main_kernel(float* __restrict__ out) {
    __shared__ __align__(16) char smem[2 * 12288];   // fp32 flavor only

    const int t = threadIdx.x, wid = t >> 5, lane = t & 31;
    const float MAGIC2 = 12583040.0f;         // 1.5*2^23 + 128
    const int bid = blockIdx.x;

    if (bid < 148) {
        // ================= TENSOR flavor =================
        const int wm = (wid >> 1) * 32, wn = (wid & 1) * 32;
        const int njobs = (bid < 56) ? 11 : 10;      // 1536 = 148*10 + 56

        for (int k = 0; k < njobs; k++) {
            const int job = bid + 148 * k;
            const int tile = job >> 3;               // 0..191
            const int c0 = (job & 7) * 8;
            const int m0 = (tile >> 4) * 128, n0 = (tile & 15) * 64;

            const int mf = (m0 + wm) >> 4;
            const int nf = (n0 + wn) >> 3;
            const uint4* pA0 = g_Ahi + (size_t)mf * 32 + lane;
            const uint4* pA1 = g_Alo + (size_t)mf * 32 + lane;
            const uint4* pB  = g_Bfr + (size_t)nf * 32 + lane;
            const size_t CA = 96 * 32, CB = 128 * 32;

            unsigned su[2][4][2];
#pragma unroll
            for (int i = 0; i < 2; i++)
#pragma unroll
                for (int j = 0; j < 4; j++) { su[i][j][0] = 0u; su[i][j][1] = 0u; }

            uint4 AH[2][2], AL[2][2], BF[2][4];

#define TLOAD(buf, r)                                                          \
            do {                                                               \
                const size_t oa = (size_t)(r) * CA, ob = (size_t)(r) * CB;     \
                AH[buf][0] = pA0[oa];     AH[buf][1] = pA0[oa + 32];           \
                AL[buf][0] = pA1[oa];     AL[buf][1] = pA1[oa + 32];           \
                BF[buf][0] = pB[ob];      BF[buf][1] = pB[ob + 32];            \
                BF[buf][2] = pB[ob + 64]; BF[buf][3] = pB[ob + 96];            \
            } while (0)

#define TCOMP(buf)                                                             \
            do {                                                               \
                _Pragma("unroll")                                              \
                for (int i = 0; i < 2; i++)                                    \
                    _Pragma("unroll")                                          \
                    for (int jp = 0; jp < 2; jp++) {                           \
                        float a0[4], a1[4];                                    \
                        const uint4 b0 = BF[buf][2 * jp];                      \
                        const uint4 b1 = BF[buf][2 * jp + 1];                  \
                        MMA_I(a0, AH[buf][i], b0.x, b0.y);                     \
                        MMA_I(a1, AH[buf][i], b1.x, b1.y);                     \
                        MMA_A(a0, AH[buf][i], b0.z, b0.w);                     \
                        MMA_A(a1, AH[buf][i], b1.z, b1.w);                     \
                        MMA_A(a0, AL[buf][i], b0.x, b0.y);                     \
                        MMA_A(a1, AL[buf][i], b1.x, b1.y);                     \
                        unsigned q0 = __float_as_uint(a0[0] + MAGIC2);         \
                        unsigned q1 = __float_as_uint(a0[1] + MAGIC2);         \
                        unsigned q2 = __float_as_uint(a0[2] + MAGIC2);         \
                        unsigned q3 = __float_as_uint(a0[3] + MAGIC2);        \
                        su[i][2 * jp][0] += __byte_perm(q0, q1, 0x5410);       \
                        su[i][2 * jp][1] += __byte_perm(q2, q3, 0x5410);       \
                        unsigned p0 = __float_as_uint(a1[0] + MAGIC2);         \
                        unsigned p1 = __float_as_uint(a1[1] + MAGIC2);         \
                        unsigned p2 = __float_as_uint(a1[2] + MAGIC2);         \
                        unsigned p3 = __float_as_uint(a1[3] + MAGIC2);         \
                        su[i][2 * jp + 1][0] += __byte_perm(p0, p1, 0x5410);   \
                        su[i][2 * jp + 1][1] += __byte_perm(p2, p3, 0x5410);   \
                    }                                                          \
            } while (0)

            TLOAD(0, c0);
#pragma unroll
            for (int r = 0; r < 8; r += 2) {
                TLOAD(1, c0 + r + 1);
                TCOMP(0);
                TLOAD(0, (r + 2 < 8) ? (c0 + r + 2) : c0);
                TCOMP(1);
            }

            // flush: half-word = sum(code)+8*128; value = 16*(half-1024)
            const int g = lane >> 2, tg = lane & 3;
#pragma unroll
            for (int i = 0; i < 2; i++)
#pragma unroll
                for (int p = 0; p < 2; p++) {
                    int row = m0 + wm + 16 * i + 8 * p + g;
                    float* orow = out + (size_t)row * N_DIM + n0 + wn + 2 * tg;
#pragma unroll
                    for (int j = 0; j < 4; j++) {
                        unsigned s = su[i][j][p];
                        atomicAdd(orow + 8 * j,
                                  16.0f * (float)((int)(s & 0xFFFFu) - 1024));
                        atomicAdd(orow + 8 * j + 1,
                                  16.0f * (float)((int)(s >> 16) - 1024));
                    }
                }
#undef TLOAD
#undef TCOMP
        }
    } else {
        // ================= FP32 flavor =================
        const unsigned sb = (unsigned)__cvta_generic_to_shared(smem);
        const int f0 = bid - 148;
        const int fj = (f0 + 74) % 148;              // offset heavy CTAs
        const int njobs = (fj < 68) ? 4 : 3;         // 512 = 148*3 + 68

        const int tm = t >> 4, tn = t & 15;
        // staging granule addressing (3 per thread per chunk)
        const int jA = t >> 5, cA = t & 31;          // sX part 1
        const int jW = t >> 4, cW = t & 15;          // sW

        const unsigned long long MAGPAIR = 0x4B4000804B400080ULL;

        for (int k = 0; k < njobs; k++) {
            const int job = fj + 148 * k;
            const int tile = job >> 3;               // 0..63 (4 x 16)
            const int c0 = (job & 7) * 8;
            const int m0 = MT + (tile >> 4) * 128;
            const int n0 = (tile & 15) * 64;
            const int mb = m0 - MT;                  // XC column base

            unsigned su[8][2];
#pragma unroll
            for (int mi = 0; mi < 8; mi++) { su[mi][0] = 0u; su[mi][1] = 0u; }

#define FSTAGE(buf, ch)                                                        \
            do {                                                               \
                unsigned d = sb + (buf) * 12288u;                              \
                const float* sx1 = g_XC + (size_t)((ch) * 16 + jA) * 512 + mb + cA * 4; \
                const float* sx2 = g_XC + (size_t)((ch) * 16 + jA + 8) * 512 + mb + cA * 4; \
                const float* sw1 = g_WC + (size_t)((ch) * 16 + jW) * 1024 + n0 + cW * 4; \
                asm volatile("cp.async.cg.shared.global [%0], [%1], 16;" ::    \
                             "r"(d + jA * 512u + cA * 16u), "l"(sx1));         \
                asm volatile("cp.async.cg.shared.global [%0], [%1], 16;" ::    \
                             "r"(d + (jA + 8) * 512u + cA * 16u), "l"(sx2));   \
                asm volatile("cp.async.cg.shared.global [%0], [%1], 16;" ::    \
                             "r"(d + 8192u + jW * 256u + cW * 16u), "l"(sw1)); \
                asm volatile("cp.async.commit_group;");                        \
            } while (0)

            FSTAGE(0, c0);
            for (int r = 0; r < 8; r++) {
                asm volatile("cp.async.wait_group 0;" ::: "memory");
                __syncthreads();
                if (r < 7) FSTAGE((r + 1) & 1, c0 + r + 1);

                const char* base = smem + (r & 1) * 12288;
                unsigned long long acc[16];
#pragma unroll
                for (int i = 0; i < 16; i++) acc[i] = 0ULL;

#pragma unroll
                for (int j = 0; j < 16; j++) {
                    const float* xrow = (const float*)(base + j * 512);
                    float av[8];
                    ((float4*)av)[0] = ((const float4*)(xrow + tm * 8))[0];
                    ((float4*)av)[1] = ((const float4*)(xrow + tm * 8))[1];
                    ulonglong2 bp = *(const ulonglong2*)(base + 8192 + j * 256 + tn * 16);
#pragma unroll
                    for (int mi = 0; mi < 8; mi++) {
                        unsigned long long ad;
                        asm("mov.b64 %0, {%1,%2};" : "=l"(ad) : "f"(av[mi]), "f"(av[mi]));
                        FFMA2(acc[2 * mi], ad, bp.x);
                        FFMA2(acc[2 * mi + 1], ad, bp.y);
                    }
                }
                // epilogue: RNE via magic pair, pack 16-bit codes
#pragma unroll
                for (int mi = 0; mi < 8; mi++) {
#pragma unroll
                    for (int np = 0; np < 2; np++) {
                        unsigned long long tt;
                        asm("add.rn.f32x2 %0, %1, %2;"
                            : "=l"(tt) : "l"(acc[2 * mi + np]), "l"(MAGPAIR));
                        unsigned lo2 = (unsigned)tt, hi2 = (unsigned)(tt >> 32);
                        su[mi][np] += __byte_perm(lo2, hi2, 0x5410);
                    }
                }
                __syncthreads();
            }

            // flush: half-word = sum(code)+8*128; value = 16*(half-1024)
#pragma unroll
            for (int mi = 0; mi < 8; mi++) {
                int row = m0 + tm * 8 + mi;
                float* orow = out + (size_t)row * N_DIM + n0 + tn * 4;
#pragma unroll
                for (int np = 0; np < 2; np++) {
                    unsigned s = su[mi][np];
                    atomicAdd(orow + 2 * np,
                              16.0f * (float)((int)(s & 0xFFFFu) - 1024));
                    atomicAdd(orow + 2 * np + 1,
                              16.0f * (float)((int)(s >> 16) - 1024));
                }
            }
#undef FSTAGE
        }
    }
}

// ---------------------------------------------------------------------------
extern "C" void kernel_launch(void* const* d_in, const int* in_sizes, int n_in,
                              void* d_out, int out_size) {
    const float* X    = (const float*)d_in[0];  // (2,1024,1024)
    const float* W    = (const float*)d_in[1];  // (1024,1024)
    const float* vmap = (const float*)d_in[2];  // (16,16)
    const float* wmap = (const float*)d_in[3];  // (16,16)
    float* out = (float*)d_out;                 // (2,1024,1024)

    prep_kernel<<<768, 256>>>(X, W, vmap, wmap, (float4*)out);
    opu_main_kernel<<<296, 256>>>(out);
}